// round 1
// baseline (speedup 1.0000x reference)
#include <cuda_runtime.h>
#include <math.h>

#define BB 32
#define TT 48
#define DIN 256
#define HH 512
#define MM 256
#define WWID 64
#define RR 4
#define IFACE 471
#define EPSV 1e-6f

// interface vector offsets
#define RK_OFF 0
#define RS_OFF 256
#define WK_OFF 260
#define WS_OFF 324
#define ER_OFF 325
#define WV_OFF 389
#define FG_OFF 453
#define AG_OFF 457
#define WG_OFF 458
#define RM_OFF 459

// -------- recurrent state (device globals; ping-pong where cross-block RAW) ----
__device__ float g_h0[2][BB*HH];
__device__ float g_c0[BB*HH];
__device__ float g_h1[2][BB*HH];
__device__ float g_c1[BB*HH];
__device__ float g_mem[BB*MM*WWID];
__device__ float g_link[BB*MM*MM];
__device__ float g_prec[BB*MM];
__device__ float g_rw[2][BB*RR*MM];
__device__ float g_ww[BB*MM];
__device__ float g_usage[BB*MM];
__device__ float g_memnorm[BB*MM];
// per-step scratch
__device__ float g_v[BB*IFACE];
__device__ float g_cww[BB*MM];
__device__ float g_cwr[BB*RR*MM];
__device__ float g_wwsum[BB];
__device__ float g_outbuf[BB*HH];

__device__ __forceinline__ float sigm(float x){ return 1.f/(1.f+expf(-x)); }
__device__ __forceinline__ float softplusf(float x){ return fmaxf(x,0.f) + log1pf(expf(-fabsf(x))); }

// ---------------- init: zero all state ----------------
__global__ void k_init(){
  int i = blockIdx.x*blockDim.x + threadIdx.x;
  if (i < BB*MM*MM)  g_link[i] = 0.f;
  if (i < BB*MM*WWID) g_mem[i] = 0.f;
  if (i < BB*RR*MM){ g_rw[0][i]=0.f; g_rw[1][i]=0.f; }
  if (i < BB*HH){ g_h0[0][i]=0.f; g_h0[1][i]=0.f; g_c0[i]=0.f;
                  g_h1[0][i]=0.f; g_h1[1][i]=0.f; g_c1[i]=0.f; }
  if (i < BB*MM){ g_prec[i]=0.f; g_ww[i]=0.f; g_usage[i]=0.f; g_memnorm[i]=0.f; }
}

// ---------------- LSTM (block: 32 batch x 4 gate x 2 units) ----------------
template<int KIN>
__device__ __forceinline__ void lstm_body(
    const float* __restrict__ xin, int xstride, int xoff,
    const float* __restrict__ Wi, const float* __restrict__ bi,
    const float* __restrict__ Wh, const float* __restrict__ bh,
    const float* __restrict__ hprev, float* __restrict__ hnew, float* __restrict__ c)
{
  __shared__ float xs[32][33];
  __shared__ float sg[2][4][32];
  const int b = threadIdx.x, g = threadIdx.y, z = threadIdx.z;
  const int u = blockIdx.x*2 + z;
  const int tid = b + 32*g + 128*z;
  const int row = g*HH + u;
  float a0 = bi[row] + bh[row], a1=0.f, a2=0.f, a3=0.f;
  const float* wr = Wi + (size_t)row*KIN;
  for (int k0 = 0; k0 < KIN; k0 += 32) {
    #pragma unroll
    for (int e = 0; e < 4; e++) {
      int idx = tid + e*256;
      xs[idx>>5][idx&31] = xin[(idx>>5)*xstride + xoff + k0 + (idx&31)];
    }
    __syncthreads();
    #pragma unroll
    for (int kk = 0; kk < 32; kk += 4) {
      a0 += xs[b][kk  ]*wr[k0+kk  ];
      a1 += xs[b][kk+1]*wr[k0+kk+1];
      a2 += xs[b][kk+2]*wr[k0+kk+2];
      a3 += xs[b][kk+3]*wr[k0+kk+3];
    }
    __syncthreads();
  }
  const float* wr2 = Wh + (size_t)row*HH;
  for (int k0 = 0; k0 < HH; k0 += 32) {
    #pragma unroll
    for (int e = 0; e < 4; e++) {
      int idx = tid + e*256;
      xs[idx>>5][idx&31] = hprev[(idx>>5)*HH + k0 + (idx&31)];
    }
    __syncthreads();
    #pragma unroll
    for (int kk = 0; kk < 32; kk += 4) {
      a0 += xs[b][kk  ]*wr2[k0+kk  ];
      a1 += xs[b][kk+1]*wr2[k0+kk+1];
      a2 += xs[b][kk+2]*wr2[k0+kk+2];
      a3 += xs[b][kk+3]*wr2[k0+kk+3];
    }
    __syncthreads();
  }
  sg[z][g][b] = a0+a1+a2+a3;
  __syncthreads();
  if (g == 0) {
    float gi = sg[z][0][b], gf = sg[z][1][b], gg = sg[z][2][b], go = sg[z][3][b];
    int ci = b*HH + u;
    float c2 = sigm(gf)*c[ci] + sigm(gi)*tanhf(gg);
    c[ci] = c2;
    hnew[ci] = sigm(go)*tanhf(c2);
  }
}

__global__ void k_lstm0(const float* __restrict__ x, int t,
    const float* __restrict__ Wi, const float* __restrict__ bi,
    const float* __restrict__ Wh, const float* __restrict__ bh, int rp)
{
  lstm_body<DIN>(x, TT*DIN, t*DIN, Wi, bi, Wh, bh, g_h0[rp], g_h0[1-rp], g_c0);
}
__global__ void k_lstm1(const float* __restrict__ Wi, const float* __restrict__ bi,
    const float* __restrict__ Wh, const float* __restrict__ bh, int rp)
{
  lstm_body<HH>(g_h0[1-rp], HH, 0, Wi, bi, Wh, bh, g_h1[rp], g_h1[1-rp], g_c1);
}

// ---------------- interface + memout projections ----------------
__global__ void k_iface(const float* __restrict__ Wif, const float* __restrict__ bif,
    const float* __restrict__ Wmo, const float* __restrict__ bmo, int rp)
{
  __shared__ float xs[32][33];
  const float* h1 = g_h1[1-rp];
  int b = threadIdx.x, jy = threadIdx.y;
  int j = blockIdx.x*8 + jy;
  int tid = b + 32*jy;
  bool valid = j < IFACE + HH;
  bool isv = j < IFACE;
  const float* wr = Wif;
  float a0 = 0.f;
  if (valid) {
    if (isv){ wr = Wif + (size_t)j*HH; a0 = bif[j]; }
    else    { wr = Wmo + (size_t)(j-IFACE)*HH; a0 = bmo[j-IFACE]; }
  }
  float a1=0.f,a2=0.f,a3=0.f;
  for (int k0=0;k0<HH;k0+=32){
    #pragma unroll
    for (int e=0;e<4;e++){
      int idx=tid+e*256;
      xs[idx>>5][idx&31]=h1[(idx>>5)*HH + k0 + (idx&31)];
    }
    __syncthreads();
    if (valid){
      #pragma unroll
      for (int kk=0; kk<32; kk+=4){
        a0+=xs[b][kk  ]*wr[k0+kk  ];
        a1+=xs[b][kk+1]*wr[k0+kk+1];
        a2+=xs[b][kk+2]*wr[k0+kk+2];
        a3+=xs[b][kk+3]*wr[k0+kk+3];
      }
    }
    __syncthreads();
  }
  if (valid){
    float r = a0+a1+a2+a3;
    if (isv) g_v[b*IFACE + j] = r;
    else     g_outbuf[b*HH + (j-IFACE)] = r;
  }
}

// ---------------- usage update + write content weighting (softmax over M) ----
__global__ void k_cww_usage(int rp)
{
  int b = blockIdx.x, m = threadIdx.x;
  const float* vb = g_v + b*IFACE;
  // usage: retention psi then free/alloc update (uses PREVIOUS ww/rw)
  const float* rwp = g_rw[rp] + b*RR*MM;
  float fg0 = sigm(vb[FG_OFF+0]), fg1 = sigm(vb[FG_OFF+1]);
  float fg2 = sigm(vb[FG_OFF+2]), fg3 = sigm(vb[FG_OFF+3]);
  float psi = (1.f - fg0*rwp[0*MM+m])*(1.f - fg1*rwp[1*MM+m])
            * (1.f - fg2*rwp[2*MM+m])*(1.f - fg3*rwp[3*MM+m]);
  float us = g_usage[b*MM+m], wwp = g_ww[b*MM+m];
  us = (us + (1.f-us)*wwp)*psi;
  g_usage[b*MM+m] = us;
  // write key content addressing on OLD memory
  __shared__ float swk[WWID];
  __shared__ float red[MM];
  __shared__ float sc[2];
  if (m < WWID) swk[m] = tanhf(vb[WK_OFF+m]);
  __syncthreads();
  if (m == 0){
    float s=0.f;
    for (int w=0;w<WWID;w++) s+=swk[w]*swk[w];
    sc[0] = sqrtf(s)+EPSV;
    sc[1] = softplusf(vb[WS_OFF]);
  }
  __syncthreads();
  const float* mr = g_mem + (size_t)(b*MM+m)*WWID;
  float dot=0.f;
  #pragma unroll 8
  for (int w=0;w<WWID;w++) dot += mr[w]*swk[w];
  float score = dot/((g_memnorm[b*MM+m]+EPSV)*sc[0]) * sc[1];
  red[m]=score; __syncthreads();
  for (int s=128;s>0;s>>=1){ if(m<s) red[m]=fmaxf(red[m],red[m+s]); __syncthreads(); }
  float mx = red[0]; __syncthreads();
  float e = expf(score-mx);
  red[m]=e; __syncthreads();
  for (int s=128;s>0;s>>=1){ if(m<s) red[m]+=red[m+s]; __syncthreads(); }
  g_cww[b*MM+m] = e/red[0];
}

// ---------------- allocation (stable sort), write weighting ww, wwsum ------
__global__ void k_alloc()
{
  int b = blockIdx.x, m = threadIdx.x;
  const float* vb = g_v + b*IFACE;
  __shared__ float skey[MM]; __shared__ int sidx[MM];
  __shared__ float sprod[MM]; __shared__ float salloc[MM]; __shared__ float red[MM];
  float uval = EPSV + (1.f-EPSV)*g_usage[b*MM+m];
  skey[m]=uval; sidx[m]=m; __syncthreads();
  // bitonic sort ascending on (key, idx) -> replicates stable argsort
  for (int k=2;k<=MM;k<<=1){
    for (int j=k>>1;j>0;j>>=1){
      int p = m ^ j;
      if (p > m){
        float ka=skey[m], kb=skey[p]; int ia=sidx[m], ib=sidx[p];
        bool agtb = (ka>kb)||(ka==kb&&ia>ib);
        bool up = ((m & k)==0);
        if (up==agtb){ skey[m]=kb;skey[p]=ka;sidx[m]=ib;sidx[p]=ia; }
      }
      __syncthreads();
    }
  }
  // inclusive product scan (Hillis-Steele)
  sprod[m]=skey[m]; __syncthreads();
  for (int off=1;off<MM;off<<=1){
    float tv = (m>=off)? sprod[m-off]:1.f;
    __syncthreads();
    sprod[m]*=tv;
    __syncthreads();
  }
  float shifted = (m==0)?1.f:sprod[m-1];
  float sa = (1.f-skey[m])*shifted;
  salloc[sidx[m]] = sa;
  __syncthreads();
  float wg = sigm(vb[WG_OFF]), ag = sigm(vb[AG_OFF]);
  float wwv = wg*(ag*salloc[m] + (1.f-ag)*g_cww[b*MM+m]);
  g_ww[b*MM+m]=wwv;
  red[m]=wwv; __syncthreads();
  for (int s=128;s>0;s>>=1){ if(m<s) red[m]+=red[m+s]; __syncthreads(); }
  if (m==0) g_wwsum[b]=red[0];
}

// ---------------- memory write + new row norms (1 warp / row) --------------
__global__ void k_memupd()
{
  int tid = threadIdx.x;
  int warp = tid>>5, lane = tid&31;
  int row = blockIdx.x*8 + warp;        // row = b*MM + m
  int b = row >> 8;
  const float* vb = g_v + b*IFACE;
  float wwm = g_ww[row];
  float s = 0.f;
  #pragma unroll
  for (int w = lane; w < WWID; w += 32){
    float er = sigm(vb[ER_OFF+w]);
    float wv = tanhf(vb[WV_OFF+w]);
    float mv = g_mem[(size_t)row*WWID+w];
    mv = mv*(1.f - wwm*er) + wwm*wv;
    g_mem[(size_t)row*WWID+w]=mv;
    s += mv*mv;
  }
  #pragma unroll
  for (int o=16;o>0;o>>=1) s += __shfl_xor_sync(0xffffffffu, s, o);
  if (lane==0) g_memnorm[row] = sqrtf(s);
}

// ---------------- temporal link update (in place, uses OLD prec) -----------
__global__ void k_link()
{
  int idx = blockIdx.x*blockDim.x + threadIdx.x;   // [0, BB*MM*MM)
  int b = idx >> 16;
  int i = (idx >> 8) & 255;
  int j = idx & 255;
  float wi = g_ww[b*MM+i], wj = g_ww[b*MM+j];
  float l = g_link[idx];
  g_link[idx] = (i==j) ? 0.f : (1.f-wi-wj)*l + wi*g_prec[b*MM+j];
}

// ---------------- read content weighting (NEW memory) + prec update --------
__global__ void k_cwr()
{
  int b = blockIdx.x>>2, r = blockIdx.x&3, m = threadIdx.x;
  const float* vb = g_v + b*IFACE;
  __shared__ float srk[WWID]; __shared__ float red[MM]; __shared__ float sc[2];
  if (m<WWID) srk[m]=tanhf(vb[RK_OFF + r*WWID + m]);
  __syncthreads();
  if (m==0){
    float s=0.f;
    for (int w=0;w<WWID;w++) s+=srk[w]*srk[w];
    sc[0]=sqrtf(s)+EPSV;
    sc[1]=softplusf(vb[RS_OFF+r]);
  }
  __syncthreads();
  const float* mr = g_mem + (size_t)(b*MM+m)*WWID;
  float dot=0.f;
  #pragma unroll 8
  for (int w=0;w<WWID;w++) dot += mr[w]*srk[w];
  float score = dot/((g_memnorm[b*MM+m]+EPSV)*sc[0]) * sc[1];
  red[m]=score; __syncthreads();
  for (int s=128;s>0;s>>=1){ if(m<s) red[m]=fmaxf(red[m],red[m+s]); __syncthreads(); }
  float mx = red[0]; __syncthreads();
  float e = expf(score-mx);
  red[m]=e; __syncthreads();
  for (int s=128;s>0;s>>=1){ if(m<s) red[m]+=red[m+s]; __syncthreads(); }
  g_cwr[(b*RR+r)*MM+m] = e/red[0];
  if (r==0) {
    g_prec[b*MM+m] = (1.f - g_wwsum[b])*g_prec[b*MM+m] + g_ww[b*MM+m];
  }
}

// ---------------- fwd/bwd link reads + new read weights --------------------
__global__ void k_rw(int rp)
{
  int b = blockIdx.x, i = threadIdx.x;
  __shared__ float srw[RR][MM];
  const float* rwp = g_rw[rp] + b*RR*MM;
  #pragma unroll
  for (int r=0;r<RR;r++) srw[r][i]=rwp[r*MM+i];
  __syncthreads();
  const float* lb = g_link + (size_t)b*MM*MM;
  float f0=0,f1=0,f2=0,f3=0,w0=0,w1=0,w2=0,w3=0;
  for (int j=0;j<MM;j++){
    float lr = lb[(size_t)i*MM+j];   // link[i][j]
    float lc = lb[(size_t)j*MM+i];   // link[j][i]
    f0+=lr*srw[0][j]; f1+=lr*srw[1][j]; f2+=lr*srw[2][j]; f3+=lr*srw[3][j];
    w0+=lc*srw[0][j]; w1+=lc*srw[1][j]; w2+=lc*srw[2][j]; w3+=lc*srw[3][j];
  }
  const float* vb = g_v + b*IFACE;
  float fw[4]={f0,f1,f2,f3}, bw[4]={w0,w1,w2,w3};
  float* rwn = g_rw[1-rp] + b*RR*MM;
  #pragma unroll
  for (int r=0;r<RR;r++){
    float x0=vb[RM_OFF+r*3], x1=vb[RM_OFF+r*3+1], x2=vb[RM_OFF+r*3+2];
    float mx=fmaxf(x0,fmaxf(x1,x2));
    float e0=expf(x0-mx), e1=expf(x1-mx), e2=expf(x2-mx);
    float inv=1.f/(e0+e1+e2);
    rwn[r*MM+i] = (e0*bw[r] + e1*fw[r] + e2*g_cwr[(b*RR+r)*MM+i])*inv;
  }
}

// ---------------- rv + output projections + final y ------------------------
__global__ void k_out(const float* __restrict__ Wrv, const float* __restrict__ brv,
    const float* __restrict__ Wout, const float* __restrict__ bout,
    float* __restrict__ yout, int t, int rp)
{
  int b = blockIdx.x, tid = threadIdx.x;
  __shared__ float srv[RR*WWID];
  __shared__ float sout[HH];
  if (tid < RR*WWID){
    int r = tid>>6, w = tid&63;
    const float* rwn = g_rw[1-rp] + (b*RR+r)*MM;
    const float* mb = g_mem + (size_t)b*MM*WWID;
    float acc=0.f;
    #pragma unroll 8
    for (int m2=0;m2<MM;m2++) acc += rwn[m2]*mb[m2*WWID + w];
    srv[tid]=acc;
  }
  __syncthreads();
  {
    float acc = g_outbuf[b*HH+tid] + brv[tid];
    const float* wr = Wrv + (size_t)tid*(RR*WWID);
    #pragma unroll 8
    for (int p=0;p<RR*WWID;p++) acc += srv[p]*wr[p];
    sout[tid]=acc;
  }
  __syncthreads();
  if (tid < DIN){
    float acc = bout[tid];
    const float* wo = Wout + (size_t)tid*HH;
    #pragma unroll 8
    for (int h=0;h<HH;h++) acc += sout[h]*wo[h];
    yout[(size_t)(b*TT + t)*DIN + tid] = acc;
  }
}

// ---------------- host ----------------
extern "C" void kernel_launch(void* const* d_in, const int* in_sizes, int n_in,
                              void* d_out, int out_size)
{
  const float* x     = (const float*)d_in[0];
  const float* Wih0  = (const float*)d_in[1];
  const float* bih0  = (const float*)d_in[2];
  const float* Whh0  = (const float*)d_in[3];
  const float* bhh0  = (const float*)d_in[4];
  const float* Wih1  = (const float*)d_in[5];
  const float* bih1  = (const float*)d_in[6];
  const float* Whh1  = (const float*)d_in[7];
  const float* bhh1  = (const float*)d_in[8];
  const float* Wif   = (const float*)d_in[9];
  const float* bif   = (const float*)d_in[10];
  const float* Wmo   = (const float*)d_in[11];
  const float* bmo   = (const float*)d_in[12];
  const float* Wrv   = (const float*)d_in[13];
  const float* brv   = (const float*)d_in[14];
  const float* Wout  = (const float*)d_in[15];
  const float* bout  = (const float*)d_in[16];
  float* y = (float*)d_out;

  k_init<<<(BB*MM*MM + 255)/256, 256>>>();
  for (int t = 0; t < TT; t++){
    int rp = t & 1;
    k_lstm0<<<HH/2, dim3(32,4,2)>>>(x, t, Wih0, bih0, Whh0, bhh0, rp);
    k_lstm1<<<HH/2, dim3(32,4,2)>>>(Wih1, bih1, Whh1, bhh1, rp);
    k_iface<<<(IFACE+HH+7)/8, dim3(32,8)>>>(Wif, bif, Wmo, bmo, rp);
    k_cww_usage<<<BB, MM>>>(rp);
    k_alloc<<<BB, MM>>>();
    k_memupd<<<BB*MM/8, 256>>>();
    k_link<<<(BB*MM*MM)/256, 256>>>();
    k_cwr<<<BB*RR, MM>>>();
    k_rw<<<BB, MM>>>(rp);
    k_out<<<BB, HH>>>(Wrv, brv, Wout, bout, y, t, rp);
  }
}

// round 3
// speedup vs baseline: 3.9768x; 3.9768x over previous
#include <cuda_runtime.h>
#include <math.h>

#define BB 32
#define TT 48
#define DIN 256
#define HH 512
#define MM 256
#define WWID 64
#define RR 4
#define IFACE 471
#define NIF 983
#define EPSV 1e-6f

#define RK_OFF 0
#define RS_OFF 256
#define WK_OFF 260
#define WS_OFF 324
#define ER_OFF 325
#define WV_OFF 389
#define FG_OFF 453
#define AG_OFF 457
#define WG_OFF 458
#define RM_OFF 459

// -------- state --------
__device__ float g_h0[2][BB*HH];
__device__ float g_c0[BB*HH];
__device__ float g_h1[2][BB*HH];
__device__ float g_c1[BB*HH];
__device__ float g_mem[BB*MM*WWID];
__device__ float g_link[(size_t)BB*MM*MM];
__device__ float g_prec[BB*MM];
__device__ float g_rw[2][BB*RR*MM];
__device__ float g_ww[BB*MM];
__device__ float g_usage[BB*MM];
__device__ float g_memnorm[BB*MM];
__device__ float g_v[BB*IFACE];
__device__ float g_cwr[BB*RR*MM];
__device__ float g_wwsum[BB];
__device__ float g_outbuf[BB*HH];
__device__ float g_rvbuf[BB*RR*WWID];
__device__ float g_out2[BB*HH];
__device__ float g_xg[(size_t)BB*TT*4*HH];   // precomputed x@Wih0^T + biases

__device__ __forceinline__ float sigm(float x){ return 1.f/(1.f+expf(-x)); }
__device__ __forceinline__ float softplusf(float x){ return fmaxf(x,0.f) + log1pf(expf(-fabsf(x))); }

// ---------------- init ----------------
__global__ void k_init(){
  size_t i = (size_t)blockIdx.x*blockDim.x + threadIdx.x;
  if (i < (size_t)BB*MM*MM) g_link[i] = 0.f;
  if (i < BB*MM*WWID) g_mem[i] = 0.f;
  if (i < BB*RR*MM){ g_rw[0][i]=0.f; g_rw[1][i]=0.f; }
  if (i < BB*HH){ g_h0[0][i]=0.f; g_h0[1][i]=0.f; g_c0[i]=0.f;
                  g_h1[0][i]=0.f; g_h1[1][i]=0.f; g_c1[i]=0.f; }
  if (i < BB*MM){ g_prec[i]=0.f; g_ww[i]=0.f; g_usage[i]=0.f; g_memnorm[i]=0.f; }
}

// ================= warp-GEMV: 4 batches x 4 rows per warp =================
#define FMA4(A,V,W) { A.x+=(V).x*(W).x; A.y+=(V).y*(W).y; A.z+=(V).z*(W).z; A.w+=(V).w*(W).w; }

__device__ __forceinline__ void wgemv16(
    const float* __restrict__ X, int xld, int b0,
    const float* __restrict__ r0, const float* __restrict__ r1,
    const float* __restrict__ r2, const float* __restrict__ r3,
    int K, float4 acc[16])
{
  const int lane = threadIdx.x & 31;
  const float4* x0 = (const float4*)(X + (size_t)(b0+0)*xld);
  const float4* x1 = (const float4*)(X + (size_t)(b0+1)*xld);
  const float4* x2 = (const float4*)(X + (size_t)(b0+2)*xld);
  const float4* x3 = (const float4*)(X + (size_t)(b0+3)*xld);
  const float4* w0 = (const float4*)r0;
  const float4* w1 = (const float4*)r1;
  const float4* w2 = (const float4*)r2;
  const float4* w3 = (const float4*)r3;
  const int K4 = K >> 2;
  for (int k = lane; k < K4; k += 32){
    float4 a = x0[k], b = x1[k], c = x2[k], d = x3[k];
    float4 wv;
    wv = w0[k]; FMA4(acc[0],a,wv)  FMA4(acc[4],b,wv)  FMA4(acc[8],c,wv)  FMA4(acc[12],d,wv)
    wv = w1[k]; FMA4(acc[1],a,wv)  FMA4(acc[5],b,wv)  FMA4(acc[9],c,wv)  FMA4(acc[13],d,wv)
    wv = w2[k]; FMA4(acc[2],a,wv)  FMA4(acc[6],b,wv)  FMA4(acc[10],c,wv) FMA4(acc[14],d,wv)
    wv = w3[k]; FMA4(acc[3],a,wv)  FMA4(acc[7],b,wv)  FMA4(acc[11],c,wv) FMA4(acc[15],d,wv)
  }
}

__device__ __forceinline__ float redw(float4 a){
  float s = (a.x+a.y)+(a.z+a.w);
  #pragma unroll
  for (int o=16;o;o>>=1) s += __shfl_xor_sync(0xffffffffu, s, o);
  return s;
}
#define ZACC float4 acc[16]; _Pragma("unroll") for (int i_=0;i_<16;i_++) acc[i_]=make_float4(0.f,0.f,0.f,0.f);
#define RED16 float r[16]; _Pragma("unroll") for (int i_=0;i_<16;i_++) r[i_]=redw(acc[i_]);

// ---------------- pregemm: xg[n][2048] = x[n] @ Wih0^T + bih0 + bhh0 -------
__global__ void __launch_bounds__(256) k_pregemm(const float* __restrict__ x,
    const float* __restrict__ Wi, const float* __restrict__ bi, const float* __restrict__ bh)
{
  int gw = blockIdx.x*8 + (threadIdx.x>>5);
  int ng = gw >> 9, u = gw & 511;
  int n0 = ng*4;
  ZACC
  wgemv16(x, DIN, n0,
          Wi + (size_t)(0*HH+u)*DIN, Wi + (size_t)(1*HH+u)*DIN,
          Wi + (size_t)(2*HH+u)*DIN, Wi + (size_t)(3*HH+u)*DIN, DIN, acc);
  RED16
  int lane = threadIdx.x & 31;
  if (lane < 4){
    int n = n0 + lane;
    #pragma unroll
    for (int g=0; g<4; g++)
      g_xg[(size_t)n*(4*HH) + g*HH + u] = r[lane*4+g] + bi[g*HH+u] + bh[g*HH+u];
  }
}

// ---------------- LSTM0: h-part + gates ----------------
__global__ void __launch_bounds__(256) k_lstm0(const float* __restrict__ Wh, int t, int rp)
{
  int gw = blockIdx.x*8 + (threadIdx.x>>5);
  int bg = gw >> 9, u = gw & 511;
  int b0 = bg*4;
  ZACC
  wgemv16(g_h0[rp], HH, b0,
          Wh + (size_t)(0*HH+u)*HH, Wh + (size_t)(1*HH+u)*HH,
          Wh + (size_t)(2*HH+u)*HH, Wh + (size_t)(3*HH+u)*HH, HH, acc);
  RED16
  int lane = threadIdx.x & 31;
  if (lane < 4){
    int b = b0 + lane;
    const float* xg = g_xg + ((size_t)b*TT + t)*(4*HH);
    float gi = r[lane*4+0] + xg[0*HH+u];
    float gf = r[lane*4+1] + xg[1*HH+u];
    float gg = r[lane*4+2] + xg[2*HH+u];
    float go = r[lane*4+3] + xg[3*HH+u];
    int ci = b*HH + u;
    float c2 = sigm(gf)*g_c0[ci] + sigm(gi)*tanhf(gg);
    g_c0[ci] = c2;
    g_h0[1-rp][ci] = sigm(go)*tanhf(c2);
  }
}

// ---------------- LSTM1 ----------------
__global__ void __launch_bounds__(256) k_lstm1(
    const float* __restrict__ Wi, const float* __restrict__ bi,
    const float* __restrict__ Wh, const float* __restrict__ bh, int rp)
{
  int gw = blockIdx.x*8 + (threadIdx.x>>5);
  int bg = gw >> 9, u = gw & 511;
  int b0 = bg*4;
  ZACC
  wgemv16(g_h0[1-rp], HH, b0,
          Wi + (size_t)(0*HH+u)*HH, Wi + (size_t)(1*HH+u)*HH,
          Wi + (size_t)(2*HH+u)*HH, Wi + (size_t)(3*HH+u)*HH, HH, acc);
  wgemv16(g_h1[rp], HH, b0,
          Wh + (size_t)(0*HH+u)*HH, Wh + (size_t)(1*HH+u)*HH,
          Wh + (size_t)(2*HH+u)*HH, Wh + (size_t)(3*HH+u)*HH, HH, acc);
  RED16
  int lane = threadIdx.x & 31;
  if (lane < 4){
    int b = b0 + lane;
    float gi = r[lane*4+0] + bi[0*HH+u] + bh[0*HH+u];
    float gf = r[lane*4+1] + bi[1*HH+u] + bh[1*HH+u];
    float gg = r[lane*4+2] + bi[2*HH+u] + bh[2*HH+u];
    float go = r[lane*4+3] + bi[3*HH+u] + bh[3*HH+u];
    int ci = b*HH + u;
    float c2 = sigm(gf)*g_c1[ci] + sigm(gi)*tanhf(gg);
    g_c1[ci] = c2;
    g_h1[1-rp][ci] = sigm(go)*tanhf(c2);
  }
}

// ---------------- interface + memout projections ----------------
__global__ void __launch_bounds__(256) k_iface(
    const float* __restrict__ Wif, const float* __restrict__ bif,
    const float* __restrict__ Wmo, const float* __restrict__ bmo, int rp)
{
  int gw = blockIdx.x*8 + (threadIdx.x>>5);     // 1968 warps
  int bg = gw / 246, rg = gw % 246;
  int b0 = bg*4, rb = rg*4;
  int rr[4]; const float* rp_[4];
  #pragma unroll
  for (int j=0;j<4;j++){
    int rrow = rb + j; if (rrow > NIF-1) rrow = NIF-1;
    rr[j] = rrow;
    rp_[j] = (rrow < IFACE) ? (Wif + (size_t)rrow*HH) : (Wmo + (size_t)(rrow-IFACE)*HH);
  }
  ZACC
  wgemv16(g_h1[1-rp], HH, b0, rp_[0], rp_[1], rp_[2], rp_[3], HH, acc);
  RED16
  int lane = threadIdx.x & 31;
  if (lane < 4){
    int b = b0 + lane;
    #pragma unroll
    for (int j=0;j<4;j++){
      int row = rr[j];
      float val = r[lane*4+j] + ((row < IFACE) ? bif[row] : bmo[row-IFACE]);
      if (row < IFACE) g_v[b*IFACE + row] = val;
      else             g_outbuf[b*HH + (row-IFACE)] = val;
    }
  }
}

// ---------------- block reductions (256 threads, 2 syncs) ----------------
__device__ __forceinline__ float blkmax(float v, volatile float* s8){
  #pragma unroll
  for (int o=16;o;o>>=1) v = fmaxf(v, __shfl_xor_sync(0xffffffffu, v, o));
  if ((threadIdx.x & 31)==0) s8[threadIdx.x>>5] = v;
  __syncthreads();
  float rr = s8[0];
  #pragma unroll
  for (int i=1;i<8;i++) rr = fmaxf(rr, s8[i]);
  __syncthreads();
  return rr;
}
__device__ __forceinline__ float blksum(float v, volatile float* s8){
  #pragma unroll
  for (int o=16;o;o>>=1) v += __shfl_xor_sync(0xffffffffu, v, o);
  if ((threadIdx.x & 31)==0) s8[threadIdx.x>>5] = v;
  __syncthreads();
  float rr = 0.f;
  #pragma unroll
  for (int i=0;i<8;i++) rr += s8[i];
  __syncthreads();
  return rr;
}

// ---- fused memory module: usage, cww, alloc(sort), ww, mem write, cwr ----
__global__ void __launch_bounds__(256) k_mem1(int rp)
{
  __shared__ float swk[WWID], ser[WWID], swv[WWID], srk[RR*WWID];
  __shared__ float s8[8];
  __shared__ float skey[MM]; __shared__ int sidx[MM];
  __shared__ float sprod[MM], salloc[MM];
  __shared__ float sc[12];
  int b = blockIdx.x, m = threadIdx.x;
  const float* vb = g_v + b*IFACE;
  if (m < WWID){ swk[m]=tanhf(vb[WK_OFF+m]); ser[m]=sigm(vb[ER_OFF+m]); swv[m]=tanhf(vb[WV_OFF+m]); }
  srk[m] = tanhf(vb[RK_OFF + m]);
  __syncthreads();
  if (m == 0){
    float s=0.f; for (int w=0;w<WWID;w++) s += swk[w]*swk[w];
    sc[0]=sqrtf(s)+EPSV; sc[1]=softplusf(vb[WS_OFF]);
    sc[10]=sigm(vb[AG_OFF]); sc[11]=sigm(vb[WG_OFF]);
  }
  if (m >= 32 && m < 36){
    int rh = m-32; float s=0.f;
    for (int w=0;w<WWID;w++) s += srk[rh*WWID+w]*srk[rh*WWID+w];
    sc[2+rh]=sqrtf(s)+EPSV; sc[6+rh]=softplusf(vb[RS_OFF+rh]);
  }
  __syncthreads();
  // old memory row in registers
  float4 mrow[16];
  float4* mr = (float4*)(g_mem + (size_t)(b*MM+m)*WWID);
  #pragma unroll
  for (int i=0;i<16;i++) mrow[i] = mr[i];
  // usage update (prev ww, prev rw)
  const float* rwp = g_rw[rp] + b*RR*MM;
  float psi = 1.f;
  #pragma unroll
  for (int rh=0;rh<RR;rh++) psi *= (1.f - sigm(vb[FG_OFF+rh])*rwp[rh*MM+m]);
  float us = g_usage[b*MM+m], wwp = g_ww[b*MM+m];
  us = (us + (1.f-us)*wwp)*psi;
  // write-content weighting on OLD memory
  float dot = 0.f;
  #pragma unroll
  for (int i=0;i<16;i++)
    dot += mrow[i].x*swk[4*i] + mrow[i].y*swk[4*i+1] + mrow[i].z*swk[4*i+2] + mrow[i].w*swk[4*i+3];
  float score = dot/((g_memnorm[b*MM+m]+EPSV)*sc[0]) * sc[1];
  float mx = blkmax(score, s8);
  float e  = expf(score - mx);
  float sm = blksum(e, s8);
  float cww = e/sm;
  // stable sort (bitonic on (key, idx))
  float uval = EPSV + (1.f-EPSV)*us;
  skey[m]=uval; sidx[m]=m; __syncthreads();
  for (int k=2;k<=MM;k<<=1){
    for (int j=k>>1;j>0;j>>=1){
      int p = m ^ j;
      if (p > m){
        float ka=skey[m], kb=skey[p]; int ia=sidx[m], ib=sidx[p];
        bool agtb = (ka>kb)||(ka==kb&&ia>ib);
        bool up = ((m & k)==0);
        if (up==agtb){ skey[m]=kb;skey[p]=ka;sidx[m]=ib;sidx[p]=ia; }
      }
      __syncthreads();
    }
  }
  sprod[m]=skey[m]; __syncthreads();
  for (int off=1;off<MM;off<<=1){
    float tv = (m>=off)? sprod[m-off] : 1.f;
    __syncthreads();
    sprod[m] *= tv;
    __syncthreads();
  }
  salloc[sidx[m]] = (1.f - skey[m]) * ((m==0)?1.f:sprod[m-1]);
  __syncthreads();
  float wwv = sc[11]*(sc[10]*salloc[m] + (1.f-sc[10])*cww);
  g_ww[b*MM+m] = wwv;
  g_usage[b*MM+m] = us;
  float wsum = blksum(wwv, s8);
  if (m==0) g_wwsum[b] = wsum;
  // memory write + new norm + read-key dots (NEW memory)
  float nrm=0.f, d0=0.f, d1=0.f, d2=0.f, d3=0.f;
  #pragma unroll
  for (int i=0;i<16;i++){
    float4 mv = mrow[i];
    int w0 = 4*i;
    mv.x = mv.x*(1.f - wwv*ser[w0  ]) + wwv*swv[w0  ];
    mv.y = mv.y*(1.f - wwv*ser[w0+1]) + wwv*swv[w0+1];
    mv.z = mv.z*(1.f - wwv*ser[w0+2]) + wwv*swv[w0+2];
    mv.w = mv.w*(1.f - wwv*ser[w0+3]) + wwv*swv[w0+3];
    nrm += mv.x*mv.x + mv.y*mv.y + mv.z*mv.z + mv.w*mv.w;
    d0 += mv.x*srk[0*WWID+w0] + mv.y*srk[0*WWID+w0+1] + mv.z*srk[0*WWID+w0+2] + mv.w*srk[0*WWID+w0+3];
    d1 += mv.x*srk[1*WWID+w0] + mv.y*srk[1*WWID+w0+1] + mv.z*srk[1*WWID+w0+2] + mv.w*srk[1*WWID+w0+3];
    d2 += mv.x*srk[2*WWID+w0] + mv.y*srk[2*WWID+w0+1] + mv.z*srk[2*WWID+w0+2] + mv.w*srk[2*WWID+w0+3];
    d3 += mv.x*srk[3*WWID+w0] + mv.y*srk[3*WWID+w0+1] + mv.z*srk[3*WWID+w0+2] + mv.w*srk[3*WWID+w0+3];
    mr[i] = mv;
  }
  float mn = sqrtf(nrm);
  g_memnorm[b*MM+m] = mn;
  float mne = mn + EPSV;
  float dd[4] = {d0,d1,d2,d3};
  #pragma unroll
  for (int rh=0;rh<RR;rh++){
    float sr = dd[rh]/(mne*sc[2+rh]) * sc[6+rh];
    float mx2 = blkmax(sr, s8);
    float e2 = expf(sr - mx2);
    float s2 = blksum(e2, s8);
    g_cwr[(b*RR+rh)*MM+m] = e2/s2;
  }
}

// ---------------- link update (new ww, OLD prec) ----------------
__global__ void k_link()
{
  int idx = blockIdx.x*blockDim.x + threadIdx.x;
  int b = idx >> 16;
  int i = (idx >> 8) & 255;
  int j = idx & 255;
  float wi = g_ww[b*MM+i], wj = g_ww[b*MM+j];
  float l = g_link[(size_t)idx];
  g_link[(size_t)idx] = (i==j) ? 0.f : (1.f-wi-wj)*l + wi*g_prec[b*MM+j];
}

// ---------- fwd/bwd + read weights + prec update (after link) -------------
__global__ void __launch_bounds__(256) k_rw2(int rp)
{
  __shared__ float srw[RR][MM];
  __shared__ float part[4][64][8];
  int blk = blockIdx.x;
  int b = blk >> 2, ig = blk & 3;
  int t = threadIdx.x;
  const float* rwp = g_rw[rp] + b*RR*MM;
  #pragma unroll
  for (int rh=0;rh<RR;rh++) srw[rh][t] = rwp[rh*MM+t];
  __syncthreads();
  int il = t & 63, q = t >> 6;
  int i = ig*64 + il;
  const float* lb = g_link + (size_t)b*MM*MM;
  float f0=0,f1=0,f2=0,f3=0,w0=0,w1=0,w2=0,w3=0;
  for (int jj=0;jj<64;jj++){
    int j = q*64 + jj;
    float lr = lb[(size_t)i*MM + j];
    float lc = lb[(size_t)j*MM + i];
    f0+=lr*srw[0][j]; f1+=lr*srw[1][j]; f2+=lr*srw[2][j]; f3+=lr*srw[3][j];
    w0+=lc*srw[0][j]; w1+=lc*srw[1][j]; w2+=lc*srw[2][j]; w3+=lc*srw[3][j];
  }
  part[q][il][0]=f0; part[q][il][1]=f1; part[q][il][2]=f2; part[q][il][3]=f3;
  part[q][il][4]=w0; part[q][il][5]=w1; part[q][il][6]=w2; part[q][il][7]=w3;
  __syncthreads();
  if (q == 0){
    const float* vb = g_v + b*IFACE;
    float* rwn = g_rw[1-rp] + b*RR*MM;
    #pragma unroll
    for (int rh=0;rh<RR;rh++){
      float fr = part[0][il][rh]   + part[1][il][rh]   + part[2][il][rh]   + part[3][il][rh];
      float wr = part[0][il][rh+4] + part[1][il][rh+4] + part[2][il][rh+4] + part[3][il][rh+4];
      float x0 = vb[RM_OFF+rh*3], x1 = vb[RM_OFF+rh*3+1], x2 = vb[RM_OFF+rh*3+2];
      float mx = fmaxf(x0, fmaxf(x1, x2));
      float e0 = expf(x0-mx), e1 = expf(x1-mx), e2 = expf(x2-mx);
      float inv = 1.f/(e0+e1+e2);
      rwn[rh*MM+i] = (e0*wr + e1*fr + e2*g_cwr[(b*RR+rh)*MM+i])*inv;
    }
    g_prec[b*MM+i] = (1.f - g_wwsum[b])*g_prec[b*MM+i] + g_ww[b*MM+i];
  }
}

// ---------------- rv = rw @ memory ----------------
__global__ void k_rv(int rp)
{
  __shared__ float srw[MM];
  int br = blockIdx.x;            // b*RR + r
  int b = br >> 2;
  int t = threadIdx.x;            // 64 threads = w
  const float* rwn = g_rw[1-rp] + br*MM;
  for (int i=t;i<MM;i+=64) srw[i] = rwn[i];
  __syncthreads();
  const float* mb = g_mem + (size_t)b*MM*WWID;
  float acc = 0.f;
  #pragma unroll 8
  for (int m2=0;m2<MM;m2++) acc += srw[m2]*mb[(size_t)m2*WWID + t];
  g_rvbuf[br*WWID + t] = acc;
}

// ---------------- out1 = outbuf + rv@Wrv^T + brv ----------------
__global__ void __launch_bounds__(256) k_wrv(const float* __restrict__ Wrv, const float* __restrict__ brv)
{
  int gw = blockIdx.x*8 + (threadIdx.x>>5);   // 1024 warps
  int bg = gw >> 7, rg = gw & 127;
  int b0 = bg*4, rb = rg*4;
  ZACC
  wgemv16(g_rvbuf, RR*WWID, b0,
          Wrv + (size_t)(rb+0)*(RR*WWID), Wrv + (size_t)(rb+1)*(RR*WWID),
          Wrv + (size_t)(rb+2)*(RR*WWID), Wrv + (size_t)(rb+3)*(RR*WWID),
          RR*WWID, acc);
  RED16
  int lane = threadIdx.x & 31;
  if (lane < 4){
    int b = b0 + lane;
    #pragma unroll
    for (int j=0;j<4;j++){
      int row = rb + j;
      g_out2[b*HH + row] = r[lane*4+j] + brv[row] + g_outbuf[b*HH + row];
    }
  }
}

// ---------------- y = out1@Wout^T + bout ----------------
__global__ void __launch_bounds__(256) k_wout(const float* __restrict__ Wout, const float* __restrict__ bout,
    float* __restrict__ y, int t)
{
  int gw = blockIdx.x*8 + (threadIdx.x>>5);   // 512 warps
  int bg = gw >> 6, rg = gw & 63;
  int b0 = bg*4, rb = rg*4;
  ZACC
  wgemv16(g_out2, HH, b0,
          Wout + (size_t)(rb+0)*HH, Wout + (size_t)(rb+1)*HH,
          Wout + (size_t)(rb+2)*HH, Wout + (size_t)(rb+3)*HH, HH, acc);
  RED16
  int lane = threadIdx.x & 31;
  if (lane < 4){
    int b = b0 + lane;
    #pragma unroll
    for (int j=0;j<4;j++){
      int row = rb + j;
      y[((size_t)b*TT + t)*DIN + row] = r[lane*4+j] + bout[row];
    }
  }
}

// ---------------- host ----------------
extern "C" void kernel_launch(void* const* d_in, const int* in_sizes, int n_in,
                              void* d_out, int out_size)
{
  const float* x     = (const float*)d_in[0];
  const float* Wih0  = (const float*)d_in[1];
  const float* bih0  = (const float*)d_in[2];
  const float* Whh0  = (const float*)d_in[3];
  const float* bhh0  = (const float*)d_in[4];
  const float* Wih1  = (const float*)d_in[5];
  const float* bih1  = (const float*)d_in[6];
  const float* Whh1  = (const float*)d_in[7];
  const float* bhh1  = (const float*)d_in[8];
  const float* Wif   = (const float*)d_in[9];
  const float* bif   = (const float*)d_in[10];
  const float* Wmo   = (const float*)d_in[11];
  const float* bmo   = (const float*)d_in[12];
  const float* Wrv   = (const float*)d_in[13];
  const float* brv   = (const float*)d_in[14];
  const float* Wout  = (const float*)d_in[15];
  const float* bout  = (const float*)d_in[16];
  float* y = (float*)d_out;

  k_init<<<(BB*MM*MM)/256, 256>>>();
  k_pregemm<<<(BB*TT/4)*(HH/8), 256>>>(x, Wih0, bih0, bhh0);   // 24576 blocks
  for (int t = 0; t < TT; t++){
    int rp = t & 1;
    k_lstm0<<<512, 256>>>(Whh0, t, rp);
    k_lstm1<<<512, 256>>>(Wih1, bih1, Whh1, bhh1, rp);
    k_iface<<<246, 256>>>(Wif, bif, Wmo, bmo, rp);
    k_mem1<<<BB, 256>>>(rp);
    k_link<<<(BB*MM*MM)/256, 256>>>();
    k_rw2<<<BB*4, 256>>>(rp);
    k_rv<<<BB*RR, 64>>>(rp);
    k_wrv<<<128, 256>>>(Wrv, brv);
    k_wout<<<64, 256>>>(Wout, bout, y, t);
  }
}